// round 2
// baseline (speedup 1.0000x reference)
#include <cuda_runtime.h>
#include <cuda_bf16.h>

#define N_NODES 100000
#define N_EDGES 3200000
#define IN_CH   256

// Scratch (device globals: allocation APIs are forbidden)
__device__ float g_xm[N_NODES];   // x @ W_mlp
__device__ float g_xl[N_NODES];   // x @ W_lin
__device__ float g_xw[N_NODES];   // x @ W_gcn
__device__ int   g_deg[N_NODES];  // in-degree (no self loops)
__device__ float g_dinv[N_NODES]; // rsqrt(deg+1)
__device__ float g_gcn[N_NODES];  // gcn accumulator

// ---------------------------------------------------------------------------
__global__ void zero_deg_kernel() {
    int n = blockIdx.x * blockDim.x + threadIdx.x;
    if (n < N_NODES) g_deg[n] = 0;
}

// One warp per node: 256 ch = 64 float4 = 2 float4 per lane. Fused 3 dots.
__global__ void dots_kernel(const float* __restrict__ x,
                            const float* __restrict__ Wm,
                            const float* __restrict__ Wl,
                            const float* __restrict__ Wg) {
    int gw   = (blockIdx.x * blockDim.x + threadIdx.x) >> 5;
    int lane = threadIdx.x & 31;
    if (gw >= N_NODES) return;

    const float4* xr  = (const float4*)(x + (size_t)gw * IN_CH);
    const float4* wm4 = (const float4*)Wm;
    const float4* wl4 = (const float4*)Wl;
    const float4* wg4 = (const float4*)Wg;

    float sm = 0.f, sl = 0.f, sg = 0.f;
#pragma unroll
    for (int k = 0; k < 2; k++) {
        int i = lane + 32 * k;
        float4 xv = xr[i];
        float4 a = __ldg(&wm4[i]);
        float4 b = __ldg(&wl4[i]);
        float4 c = __ldg(&wg4[i]);
        sm += xv.x * a.x + xv.y * a.y + xv.z * a.z + xv.w * a.w;
        sl += xv.x * b.x + xv.y * b.y + xv.z * b.z + xv.w * b.w;
        sg += xv.x * c.x + xv.y * c.y + xv.z * c.z + xv.w * c.w;
    }
#pragma unroll
    for (int o = 16; o > 0; o >>= 1) {
        sm += __shfl_xor_sync(0xffffffffu, sm, o);
        sl += __shfl_xor_sync(0xffffffffu, sl, o);
        sg += __shfl_xor_sync(0xffffffffu, sg, o);
    }
    if (lane == 0) {
        g_xm[gw] = sm;
        g_xl[gw] = sl;
        g_xw[gw] = sg;
    }
}

// Degree count over edge targets (edge_index is int32: JAX default x64-disabled).
__global__ void deg_kernel(const int* __restrict__ dst) {
    int i = blockIdx.x * blockDim.x + threadIdx.x;
    if (i < N_EDGES) {
        atomicAdd(&g_deg[dst[i]], 1);
    }
}

// dinv = rsqrt(deg + 1 self-loop); seed gcn with self-loop message.
__global__ void dinv_kernel() {
    int n = blockIdx.x * blockDim.x + threadIdx.x;
    if (n < N_NODES) {
        float d  = (float)g_deg[n] + 1.0f;   // always > 0
        float di = rsqrtf(d);
        g_dinv[n] = di;
        g_gcn[n]  = di * di * g_xw[n];       // self-loop: norm = dinv[n]^2
    }
}

// Edge messages: gcn[dst] += dinv[src]*dinv[dst]*xw[src]
__global__ void msg_kernel(const int* __restrict__ src,
                           const int* __restrict__ dst) {
    int i = blockIdx.x * blockDim.x + threadIdx.x;
    if (i < N_EDGES) {
        int s = src[i];
        int d = dst[i];
        float m = g_dinv[s] * g_dinv[d] * g_xw[s];
        atomicAdd(&g_gcn[d], m);
    }
}

__device__ __forceinline__ float sigmoidf_(float v) {
    return 1.0f / (1.0f + expf(-v));
}

// Final fusion: scores -> softmax attention -> fitness
__global__ void final_kernel(const float* __restrict__ alpha_p,
                             const float* __restrict__ beta_p,
                             const float* __restrict__ W_att,
                             const float* __restrict__ b_att,
                             float* __restrict__ out) {
    int n = blockIdx.x * blockDim.x + threadIdx.x;
    if (n >= N_NODES) return;

    float alpha = __ldg(alpha_p);
    float beta  = __ldg(beta_p);

    float deg = (float)g_deg[n];
    float s1 = sigmoidf_(alpha * sqrtf(deg) + beta);
    float s2 = sigmoidf_(g_xm[n]);
    float s3 = sigmoidf_(g_gcn[n] + g_xl[n]);

    // logits[j] = s1*W[j][0] + s2*W[j][1] + s3*W[j][2] + b[j]
    float l0 = s1 * __ldg(&W_att[0]) + s2 * __ldg(&W_att[1]) + s3 * __ldg(&W_att[2]) + __ldg(&b_att[0]);
    float l1 = s1 * __ldg(&W_att[3]) + s2 * __ldg(&W_att[4]) + s3 * __ldg(&W_att[5]) + __ldg(&b_att[1]);
    float l2 = s1 * __ldg(&W_att[6]) + s2 * __ldg(&W_att[7]) + s3 * __ldg(&W_att[8]) + __ldg(&b_att[2]);

    float m  = fmaxf(l0, fmaxf(l1, l2));
    float e0 = expf(l0 - m), e1 = expf(l1 - m), e2 = expf(l2 - m);
    float inv = 1.0f / (e0 + e1 + e2);
    out[n] = (e0 * s1 + e1 * s2 + e2 * s3) * inv;
}

// ---------------------------------------------------------------------------
extern "C" void kernel_launch(void* const* d_in, const int* in_sizes, int n_in,
                              void* d_out, int out_size) {
    const float* x     = (const float*)d_in[0];
    const int*   eidx  = (const int*)d_in[1];   // [2, N_EDGES] int32
    const float* alpha = (const float*)d_in[2];
    const float* beta  = (const float*)d_in[3];
    const float* Wm    = (const float*)d_in[4];
    const float* Wl    = (const float*)d_in[5];
    const float* Wg    = (const float*)d_in[6];
    const float* Watt  = (const float*)d_in[7];
    const float* batt  = (const float*)d_in[8];
    float* out = (float*)d_out;

    const int* src = eidx;            // edge_index[0]
    const int* dst = eidx + N_EDGES;  // edge_index[1]

    const int T = 256;
    int nodeBlocks = (N_NODES + T - 1) / T;
    int edgeBlocks = (N_EDGES + T - 1) / T;
    int dotBlocks  = (N_NODES * 32 + T - 1) / T;  // 1 warp per node

    zero_deg_kernel<<<nodeBlocks, T>>>();
    dots_kernel<<<dotBlocks, T>>>(x, Wm, Wl, Wg);
    deg_kernel<<<edgeBlocks, T>>>(dst);
    dinv_kernel<<<nodeBlocks, T>>>();
    msg_kernel<<<edgeBlocks, T>>>(src, dst);
    final_kernel<<<nodeBlocks, T>>>(alpha, beta, Watt, batt, out);
}

// round 3
// speedup vs baseline: 1.1183x; 1.1183x over previous
#include <cuda_runtime.h>
#include <cuda_bf16.h>

#define N_NODES 100000
#define N_EDGES 3200000
#define IN_CH   256

// Scratch (device globals: allocation APIs are forbidden)
__device__ float g_xm[N_NODES];    // x @ W_mlp
__device__ float g_xl[N_NODES];    // x @ W_lin
__device__ float g_xw[N_NODES];    // x @ W_gcn
__device__ float g_degf[N_NODES];  // in-degree (float, exact for counts < 2^24)
__device__ float g_gcn[N_NODES];   // accumulates sum_s dinv[s]*xw[s]

#define DOT_BLOCKS 12500   // 100000 nodes * 32 threads / 256
#define DEG_BLOCKS 3125    // 3.2M edges / 4 per thread / 256
#define MSG_BLOCKS 3125

// ---------------------------------------------------------------------------
// Fused: blocks [0, DOT_BLOCKS) compute the three per-node dot products
// (warp per node, float4); blocks [DOT_BLOCKS, ...) count in-degree with
// int4-vectorized edge loads + float atomics. Both are HBM-bound and
// independent, so they stream concurrently.
__global__ void __launch_bounds__(256) fused_dots_deg_kernel(
        const float* __restrict__ x,
        const float* __restrict__ Wm,
        const float* __restrict__ Wl,
        const float* __restrict__ Wg,
        const int*   __restrict__ dst) {
    if (blockIdx.x < DOT_BLOCKS) {
        int gw   = (blockIdx.x * 256 + threadIdx.x) >> 5;
        int lane = threadIdx.x & 31;
        if (gw >= N_NODES) return;

        const float4* xr  = (const float4*)(x + (size_t)gw * IN_CH);
        const float4* wm4 = (const float4*)Wm;
        const float4* wl4 = (const float4*)Wl;
        const float4* wg4 = (const float4*)Wg;

        float sm = 0.f, sl = 0.f, sg = 0.f;
#pragma unroll
        for (int k = 0; k < 2; k++) {
            int i = lane + 32 * k;
            float4 xv = xr[i];
            float4 a = __ldg(&wm4[i]);
            float4 b = __ldg(&wl4[i]);
            float4 c = __ldg(&wg4[i]);
            sm += xv.x * a.x + xv.y * a.y + xv.z * a.z + xv.w * a.w;
            sl += xv.x * b.x + xv.y * b.y + xv.z * b.z + xv.w * b.w;
            sg += xv.x * c.x + xv.y * c.y + xv.z * c.z + xv.w * c.w;
        }
#pragma unroll
        for (int o = 16; o > 0; o >>= 1) {
            sm += __shfl_xor_sync(0xffffffffu, sm, o);
            sl += __shfl_xor_sync(0xffffffffu, sl, o);
            sg += __shfl_xor_sync(0xffffffffu, sg, o);
        }
        if (lane == 0) {
            g_xm[gw] = sm;
            g_xl[gw] = sl;
            g_xw[gw] = sg;
        }
    } else {
        int t = (blockIdx.x - DOT_BLOCKS) * 256 + threadIdx.x;
        if (t < N_EDGES / 4) {
            int4 d4 = ((const int4*)dst)[t];
            atomicAdd(&g_degf[d4.x], 1.0f);
            atomicAdd(&g_degf[d4.y], 1.0f);
            atomicAdd(&g_degf[d4.z], 1.0f);
            atomicAdd(&g_degf[d4.w], 1.0f);
        }
    }
}

// ---------------------------------------------------------------------------
// Edge messages: gcn[d] += rsqrt(deg[s]+1) * xw[s]   (dinv[d] applied in final)
__global__ void __launch_bounds__(256) msg_kernel(const int* __restrict__ src,
                                                  const int* __restrict__ dst) {
    int t = blockIdx.x * 256 + threadIdx.x;
    if (t >= N_EDGES / 4) return;
    int4 s4 = ((const int4*)src)[t];
    int4 d4 = ((const int4*)dst)[t];

    float m0 = rsqrtf(g_degf[s4.x] + 1.0f) * g_xw[s4.x];
    float m1 = rsqrtf(g_degf[s4.y] + 1.0f) * g_xw[s4.y];
    float m2 = rsqrtf(g_degf[s4.z] + 1.0f) * g_xw[s4.z];
    float m3 = rsqrtf(g_degf[s4.w] + 1.0f) * g_xw[s4.w];

    atomicAdd(&g_gcn[d4.x], m0);
    atomicAdd(&g_gcn[d4.y], m1);
    atomicAdd(&g_gcn[d4.z], m2);
    atomicAdd(&g_gcn[d4.w], m3);
}

__device__ __forceinline__ float sigmoidf_(float v) {
    return 1.0f / (1.0f + expf(-v));
}

// ---------------------------------------------------------------------------
// Final fusion: scores -> softmax attention -> fitness
__global__ void __launch_bounds__(256) final_kernel(
        const float* __restrict__ alpha_p,
        const float* __restrict__ beta_p,
        const float* __restrict__ W_att,
        const float* __restrict__ b_att,
        float* __restrict__ out) {
    int n = blockIdx.x * 256 + threadIdx.x;
    if (n >= N_NODES) return;

    float alpha = __ldg(alpha_p);
    float beta  = __ldg(beta_p);

    float degf = g_degf[n];
    float dinv = rsqrtf(degf + 1.0f);
    // gcn_out = dinv[n] * (sum_s dinv[s]*xw[s]  +  dinv[n]*xw[n])
    float gcn = dinv * (g_gcn[n] + dinv * g_xw[n]);

    float s1 = sigmoidf_(alpha * sqrtf(degf) + beta);
    float s2 = sigmoidf_(g_xm[n]);
    float s3 = sigmoidf_(gcn + g_xl[n]);

    float l0 = s1 * __ldg(&W_att[0]) + s2 * __ldg(&W_att[1]) + s3 * __ldg(&W_att[2]) + __ldg(&b_att[0]);
    float l1 = s1 * __ldg(&W_att[3]) + s2 * __ldg(&W_att[4]) + s3 * __ldg(&W_att[5]) + __ldg(&b_att[1]);
    float l2 = s1 * __ldg(&W_att[6]) + s2 * __ldg(&W_att[7]) + s3 * __ldg(&W_att[8]) + __ldg(&b_att[2]);

    float m  = fmaxf(l0, fmaxf(l1, l2));
    float e0 = expf(l0 - m), e1 = expf(l1 - m), e2 = expf(l2 - m);
    float inv = 1.0f / (e0 + e1 + e2);
    out[n] = (e0 * s1 + e1 * s2 + e2 * s3) * inv;
}

// ---------------------------------------------------------------------------
extern "C" void kernel_launch(void* const* d_in, const int* in_sizes, int n_in,
                              void* d_out, int out_size) {
    const float* x     = (const float*)d_in[0];
    const int*   eidx  = (const int*)d_in[1];   // [2, N_EDGES] int32
    const float* alpha = (const float*)d_in[2];
    const float* beta  = (const float*)d_in[3];
    const float* Wm    = (const float*)d_in[4];
    const float* Wl    = (const float*)d_in[5];
    const float* Wg    = (const float*)d_in[6];
    const float* Watt  = (const float*)d_in[7];
    const float* batt  = (const float*)d_in[8];
    float* out = (float*)d_out;

    const int* src = eidx;            // edge_index[0]
    const int* dst = eidx + N_EDGES;  // edge_index[1]

    // Zero the two accumulators with graph memset nodes (no extra kernels).
    void* degf_ptr = nullptr;
    void* gcn_ptr  = nullptr;
    cudaGetSymbolAddress(&degf_ptr, g_degf);
    cudaGetSymbolAddress(&gcn_ptr,  g_gcn);
    cudaMemsetAsync(degf_ptr, 0, N_NODES * sizeof(float));
    cudaMemsetAsync(gcn_ptr,  0, N_NODES * sizeof(float));

    fused_dots_deg_kernel<<<DOT_BLOCKS + DEG_BLOCKS, 256>>>(x, Wm, Wl, Wg, dst);
    msg_kernel<<<MSG_BLOCKS, 256>>>(src, dst);

    int nodeBlocks = (N_NODES + 255) / 256;
    final_kernel<<<nodeBlocks, 256>>>(alpha, beta, Watt, batt, out);
}

// round 4
// speedup vs baseline: 1.1420x; 1.0211x over previous
#include <cuda_runtime.h>
#include <cuda_bf16.h>

#define N_NODES 100000
#define N_EDGES 3200000
#define IN_CH   256

// Scratch (device globals: allocation APIs are forbidden)
__device__ float g_xm[N_NODES];    // x @ W_mlp
__device__ float g_xl[N_NODES];    // x @ W_lin
__device__ float g_xw[N_NODES];    // x @ W_gcn
__device__ float g_degf[N_NODES];  // in-degree (float, exact: deg << 2^24)
__device__ float g_gcn[N_NODES];   // accumulates sum_s dinv[s]*xw[s]

#define DOT_BLOCKS 1184            // 8 blocks/SM * 148; 9472 warps grid-stride
#define DOT_WARPS  (DOT_BLOCKS * 8)
#define EGROUPS    (N_EDGES / 8)   // 400000: each thread does 2 int4 groups
#define EDG_BLOCKS ((EGROUPS + 255) / 256)  // 1563

// ---------------------------------------------------------------------------
// Fused: blocks [0, DOT_BLOCKS) = persistent warps computing the 3 per-node
// dots (weights hoisted to registers, 2 nodes per iteration for ILP/MLP);
// blocks [DOT_BLOCKS, ...) = degree count, 8 edges per thread.
__global__ void __launch_bounds__(256) fused_dots_deg_kernel(
        const float* __restrict__ x,
        const float* __restrict__ Wm,
        const float* __restrict__ Wl,
        const float* __restrict__ Wg,
        const int*   __restrict__ dst) {
    if (blockIdx.x < DOT_BLOCKS) {
        int wid  = (blockIdx.x * 256 + threadIdx.x) >> 5;
        int lane = threadIdx.x & 31;
        int i0 = lane, i1 = lane + 32;

        // Hoist weights into registers once per warp.
        const float4* wm4 = (const float4*)Wm;
        const float4* wl4 = (const float4*)Wl;
        const float4* wg4 = (const float4*)Wg;
        float4 m0 = __ldg(&wm4[i0]), m1 = __ldg(&wm4[i1]);
        float4 l0 = __ldg(&wl4[i0]), l1 = __ldg(&wl4[i1]);
        float4 g0 = __ldg(&wg4[i0]), g1 = __ldg(&wg4[i1]);

        for (int n = wid; n < N_NODES; n += 2 * DOT_WARPS) {
            int nb = n + DOT_WARPS;
            bool hasB = (nb < N_NODES);

            const float4* xa = (const float4*)(x + (size_t)n * IN_CH);
            const float4* xb = (const float4*)(x + (size_t)(hasB ? nb : n) * IN_CH);

            // Issue all 4 loads up front (MLP = 4 float4 per lane).
            float4 a0 = xa[i0];
            float4 a1 = xa[i1];
            float4 b0 = xb[i0];
            float4 b1 = xb[i1];

            float smA = a0.x*m0.x + a0.y*m0.y + a0.z*m0.z + a0.w*m0.w
                      + a1.x*m1.x + a1.y*m1.y + a1.z*m1.z + a1.w*m1.w;
            float slA = a0.x*l0.x + a0.y*l0.y + a0.z*l0.z + a0.w*l0.w
                      + a1.x*l1.x + a1.y*l1.y + a1.z*l1.z + a1.w*l1.w;
            float sgA = a0.x*g0.x + a0.y*g0.y + a0.z*g0.z + a0.w*g0.w
                      + a1.x*g1.x + a1.y*g1.y + a1.z*g1.z + a1.w*g1.w;
            float smB = b0.x*m0.x + b0.y*m0.y + b0.z*m0.z + b0.w*m0.w
                      + b1.x*m1.x + b1.y*m1.y + b1.z*m1.z + b1.w*m1.w;
            float slB = b0.x*l0.x + b0.y*l0.y + b0.z*l0.z + b0.w*l0.w
                      + b1.x*l1.x + b1.y*l1.y + b1.z*l1.z + b1.w*l1.w;
            float sgB = b0.x*g0.x + b0.y*g0.y + b0.z*g0.z + b0.w*g0.w
                      + b1.x*g1.x + b1.y*g1.y + b1.z*g1.z + b1.w*g1.w;

            // Interleaved butterfly reductions: 6 independent chains.
#pragma unroll
            for (int o = 16; o > 0; o >>= 1) {
                smA += __shfl_xor_sync(0xffffffffu, smA, o);
                slA += __shfl_xor_sync(0xffffffffu, slA, o);
                sgA += __shfl_xor_sync(0xffffffffu, sgA, o);
                smB += __shfl_xor_sync(0xffffffffu, smB, o);
                slB += __shfl_xor_sync(0xffffffffu, slB, o);
                sgB += __shfl_xor_sync(0xffffffffu, sgB, o);
            }
            if (lane == 0) {
                g_xm[n] = smA; g_xl[n] = slA; g_xw[n] = sgA;
                if (hasB) { g_xm[nb] = smB; g_xl[nb] = slB; g_xw[nb] = sgB; }
            }
        }
    } else {
        int t = (blockIdx.x - DOT_BLOCKS) * 256 + threadIdx.x;
        if (t < EGROUPS) {
            const int4* d4p = (const int4*)dst;
            int4 a = d4p[t];
            int4 b = d4p[t + EGROUPS];
            atomicAdd(&g_degf[a.x], 1.0f);
            atomicAdd(&g_degf[a.y], 1.0f);
            atomicAdd(&g_degf[a.z], 1.0f);
            atomicAdd(&g_degf[a.w], 1.0f);
            atomicAdd(&g_degf[b.x], 1.0f);
            atomicAdd(&g_degf[b.y], 1.0f);
            atomicAdd(&g_degf[b.z], 1.0f);
            atomicAdd(&g_degf[b.w], 1.0f);
        }
    }
}

// ---------------------------------------------------------------------------
// Edge messages: gcn[d] += rsqrt(deg[s]+1) * xw[s]  (dinv[d] applied in final)
// 8 edges per thread for deep MLP on the L2-resident gathers.
__global__ void __launch_bounds__(256) msg_kernel(const int* __restrict__ src,
                                                  const int* __restrict__ dst) {
    int t = blockIdx.x * 256 + threadIdx.x;
    if (t >= EGROUPS) return;
    const int4* s4p = (const int4*)src;
    const int4* d4p = (const int4*)dst;
    int4 sa = s4p[t];
    int4 sb = s4p[t + EGROUPS];
    int4 da = d4p[t];
    int4 db = d4p[t + EGROUPS];

    // Issue all 16 gathers before computing (L2-resident, ~234 cyc).
    float dg0 = __ldg(&g_degf[sa.x]), xw0 = __ldg(&g_xw[sa.x]);
    float dg1 = __ldg(&g_degf[sa.y]), xw1 = __ldg(&g_xw[sa.y]);
    float dg2 = __ldg(&g_degf[sa.z]), xw2 = __ldg(&g_xw[sa.z]);
    float dg3 = __ldg(&g_degf[sa.w]), xw3 = __ldg(&g_xw[sa.w]);
    float dg4 = __ldg(&g_degf[sb.x]), xw4 = __ldg(&g_xw[sb.x]);
    float dg5 = __ldg(&g_degf[sb.y]), xw5 = __ldg(&g_xw[sb.y]);
    float dg6 = __ldg(&g_degf[sb.z]), xw6 = __ldg(&g_xw[sb.z]);
    float dg7 = __ldg(&g_degf[sb.w]), xw7 = __ldg(&g_xw[sb.w]);

    atomicAdd(&g_gcn[da.x], rsqrtf(dg0 + 1.0f) * xw0);
    atomicAdd(&g_gcn[da.y], rsqrtf(dg1 + 1.0f) * xw1);
    atomicAdd(&g_gcn[da.z], rsqrtf(dg2 + 1.0f) * xw2);
    atomicAdd(&g_gcn[da.w], rsqrtf(dg3 + 1.0f) * xw3);
    atomicAdd(&g_gcn[db.x], rsqrtf(dg4 + 1.0f) * xw4);
    atomicAdd(&g_gcn[db.y], rsqrtf(dg5 + 1.0f) * xw5);
    atomicAdd(&g_gcn[db.z], rsqrtf(dg6 + 1.0f) * xw6);
    atomicAdd(&g_gcn[db.w], rsqrtf(dg7 + 1.0f) * xw7);
}

__device__ __forceinline__ float sigmoidf_(float v) {
    return 1.0f / (1.0f + expf(-v));
}

// ---------------------------------------------------------------------------
__global__ void __launch_bounds__(256) final_kernel(
        const float* __restrict__ alpha_p,
        const float* __restrict__ beta_p,
        const float* __restrict__ W_att,
        const float* __restrict__ b_att,
        float* __restrict__ out) {
    int n = blockIdx.x * 256 + threadIdx.x;
    if (n >= N_NODES) return;

    float alpha = __ldg(alpha_p);
    float beta  = __ldg(beta_p);

    float degf = g_degf[n];
    float dinv = rsqrtf(degf + 1.0f);
    float gcn = dinv * (g_gcn[n] + dinv * g_xw[n]);

    float s1 = sigmoidf_(alpha * sqrtf(degf) + beta);
    float s2 = sigmoidf_(g_xm[n]);
    float s3 = sigmoidf_(gcn + g_xl[n]);

    float l0 = s1 * __ldg(&W_att[0]) + s2 * __ldg(&W_att[1]) + s3 * __ldg(&W_att[2]) + __ldg(&b_att[0]);
    float l1 = s1 * __ldg(&W_att[3]) + s2 * __ldg(&W_att[4]) + s3 * __ldg(&W_att[5]) + __ldg(&b_att[1]);
    float l2 = s1 * __ldg(&W_att[6]) + s2 * __ldg(&W_att[7]) + s3 * __ldg(&W_att[8]) + __ldg(&b_att[2]);

    float m  = fmaxf(l0, fmaxf(l1, l2));
    float e0 = expf(l0 - m), e1 = expf(l1 - m), e2 = expf(l2 - m);
    float inv = 1.0f / (e0 + e1 + e2);
    out[n] = (e0 * s1 + e1 * s2 + e2 * s3) * inv;
}

// ---------------------------------------------------------------------------
extern "C" void kernel_launch(void* const* d_in, const int* in_sizes, int n_in,
                              void* d_out, int out_size) {
    const float* x     = (const float*)d_in[0];
    const int*   eidx  = (const int*)d_in[1];   // [2, N_EDGES] int32
    const float* alpha = (const float*)d_in[2];
    const float* beta  = (const float*)d_in[3];
    const float* Wm    = (const float*)d_in[4];
    const float* Wl    = (const float*)d_in[5];
    const float* Wg    = (const float*)d_in[6];
    const float* Watt  = (const float*)d_in[7];
    const float* batt  = (const float*)d_in[8];
    float* out = (float*)d_out;

    const int* src = eidx;            // edge_index[0]
    const int* dst = eidx + N_EDGES;  // edge_index[1]

    void* degf_ptr = nullptr;
    void* gcn_ptr  = nullptr;
    cudaGetSymbolAddress(&degf_ptr, g_degf);
    cudaGetSymbolAddress(&gcn_ptr,  g_gcn);
    cudaMemsetAsync(degf_ptr, 0, N_NODES * sizeof(float));
    cudaMemsetAsync(gcn_ptr,  0, N_NODES * sizeof(float));

    fused_dots_deg_kernel<<<DOT_BLOCKS + EDG_BLOCKS, 256>>>(x, Wm, Wl, Wg, dst);
    msg_kernel<<<EDG_BLOCKS, 256>>>(src, dst);

    int nodeBlocks = (N_NODES + 255) / 256;
    final_kernel<<<nodeBlocks, 256>>>(alpha, beta, Watt, batt, out);
}

// round 5
// speedup vs baseline: 1.2318x; 1.0786x over previous
#include <cuda_runtime.h>
#include <cuda_bf16.h>

#define N_NODES 100000
#define N_EDGES 3200000
#define IN_CH   256

// Scratch (device globals: allocation APIs are forbidden)
__device__ float g_xm[N_NODES];    // x @ W_mlp
__device__ float g_xl[N_NODES];    // x @ W_lin
__device__ float g_xw[N_NODES];    // x @ W_gcn
__device__ float g_degf[N_NODES];  // in-degree (float, exact: deg << 2^24)
__device__ float g_h[N_NODES];     // rsqrt(deg+1) * xw
__device__ float g_gcn[N_NODES];   // accumulates sum_s h[s]

#define DOT_BLOCKS 592             // 4 blocks/SM * 148
#define DOT_WARPS  (DOT_BLOCKS * 8)        // 4736 warps
#define NODES_PER_ITER 4
#define EGROUPS    (N_EDGES / 8)   // 400000: each thread does 2 int4 groups
#define EDG_BLOCKS ((EGROUPS + 255) / 256) // 1563

// ---------------------------------------------------------------------------
// Dots: one warp handles 4 nodes per grid-stride iteration. Weights live in
// registers; 8 independent 128B loads in flight; 12 interleaved shfl chains.
__device__ __forceinline__ void dot3(const float4 a0, const float4 a1,
                                     const float4 m0, const float4 m1,
                                     const float4 l0, const float4 l1,
                                     const float4 g0, const float4 g1,
                                     float& sm, float& sl, float& sg) {
    sm = a0.x*m0.x + a0.y*m0.y + a0.z*m0.z + a0.w*m0.w
       + a1.x*m1.x + a1.y*m1.y + a1.z*m1.z + a1.w*m1.w;
    sl = a0.x*l0.x + a0.y*l0.y + a0.z*l0.z + a0.w*l0.w
       + a1.x*l1.x + a1.y*l1.y + a1.z*l1.z + a1.w*l1.w;
    sg = a0.x*g0.x + a0.y*g0.y + a0.z*g0.z + a0.w*g0.w
       + a1.x*g1.x + a1.y*g1.y + a1.z*g1.z + a1.w*g1.w;
}

__global__ void __launch_bounds__(256) fused_dots_deg_kernel(
        const float* __restrict__ x,
        const float* __restrict__ Wm,
        const float* __restrict__ Wl,
        const float* __restrict__ Wg,
        const int*   __restrict__ dst) {
    if (blockIdx.x < DOT_BLOCKS) {
        int wid  = (blockIdx.x * 256 + threadIdx.x) >> 5;
        int lane = threadIdx.x & 31;
        int i0 = lane, i1 = lane + 32;

        const float4* wm4 = (const float4*)Wm;
        const float4* wl4 = (const float4*)Wl;
        const float4* wg4 = (const float4*)Wg;
        float4 m0 = __ldg(&wm4[i0]), m1 = __ldg(&wm4[i1]);
        float4 l0 = __ldg(&wl4[i0]), l1 = __ldg(&wl4[i1]);
        float4 g0 = __ldg(&wg4[i0]), g1 = __ldg(&wg4[i1]);

        const int stride = DOT_WARPS;
        for (int n0 = wid; n0 < N_NODES; n0 += NODES_PER_ITER * stride) {
            int n1 = n0 + stride;
            int n2 = n0 + 2 * stride;
            int n3 = n0 + 3 * stride;
            bool h1 = n1 < N_NODES, h2 = n2 < N_NODES, h3 = n3 < N_NODES;

            const float4* x0 = (const float4*)(x + (size_t)n0 * IN_CH);
            const float4* x1 = (const float4*)(x + (size_t)(h1 ? n1 : n0) * IN_CH);
            const float4* x2 = (const float4*)(x + (size_t)(h2 ? n2 : n0) * IN_CH);
            const float4* x3 = (const float4*)(x + (size_t)(h3 ? n3 : n0) * IN_CH);

            // 8 independent loads issued before any use.
            float4 a0 = x0[i0], a1 = x0[i1];
            float4 b0 = x1[i0], b1 = x1[i1];
            float4 c0 = x2[i0], c1 = x2[i1];
            float4 d0 = x3[i0], d1 = x3[i1];

            float smA, slA, sgA, smB, slB, sgB, smC, slC, sgC, smD, slD, sgD;
            dot3(a0, a1, m0, m1, l0, l1, g0, g1, smA, slA, sgA);
            dot3(b0, b1, m0, m1, l0, l1, g0, g1, smB, slB, sgB);
            dot3(c0, c1, m0, m1, l0, l1, g0, g1, smC, slC, sgC);
            dot3(d0, d1, m0, m1, l0, l1, g0, g1, smD, slD, sgD);

#pragma unroll
            for (int o = 16; o > 0; o >>= 1) {
                smA += __shfl_xor_sync(0xffffffffu, smA, o);
                slA += __shfl_xor_sync(0xffffffffu, slA, o);
                sgA += __shfl_xor_sync(0xffffffffu, sgA, o);
                smB += __shfl_xor_sync(0xffffffffu, smB, o);
                slB += __shfl_xor_sync(0xffffffffu, slB, o);
                sgB += __shfl_xor_sync(0xffffffffu, sgB, o);
                smC += __shfl_xor_sync(0xffffffffu, smC, o);
                slC += __shfl_xor_sync(0xffffffffu, slC, o);
                sgC += __shfl_xor_sync(0xffffffffu, sgC, o);
                smD += __shfl_xor_sync(0xffffffffu, smD, o);
                slD += __shfl_xor_sync(0xffffffffu, slD, o);
                sgD += __shfl_xor_sync(0xffffffffu, sgD, o);
            }
            if (lane == 0) {
                g_xm[n0] = smA; g_xl[n0] = slA; g_xw[n0] = sgA;
                if (h1) { g_xm[n1] = smB; g_xl[n1] = slB; g_xw[n1] = sgB; }
                if (h2) { g_xm[n2] = smC; g_xl[n2] = slC; g_xw[n2] = sgC; }
                if (h3) { g_xm[n3] = smD; g_xl[n3] = slD; g_xw[n3] = sgD; }
            }
        }
    } else {
        int t = (blockIdx.x - DOT_BLOCKS) * 256 + threadIdx.x;
        if (t < EGROUPS) {
            const int4* d4p = (const int4*)dst;
            int4 a = d4p[t];
            int4 b = d4p[t + EGROUPS];
            atomicAdd(&g_degf[a.x], 1.0f);
            atomicAdd(&g_degf[a.y], 1.0f);
            atomicAdd(&g_degf[a.z], 1.0f);
            atomicAdd(&g_degf[a.w], 1.0f);
            atomicAdd(&g_degf[b.x], 1.0f);
            atomicAdd(&g_degf[b.y], 1.0f);
            atomicAdd(&g_degf[b.z], 1.0f);
            atomicAdd(&g_degf[b.w], 1.0f);
        }
    }
}

// ---------------------------------------------------------------------------
// h[n] = rsqrt(deg+1) * xw[n] — single gather stream for msg.
__global__ void __launch_bounds__(256) h_kernel() {
    int n = blockIdx.x * 256 + threadIdx.x;
    if (n < N_NODES) {
        g_h[n] = rsqrtf(g_degf[n] + 1.0f) * g_xw[n];
    }
}

// ---------------------------------------------------------------------------
// Edge messages: gcn[d] += h[s]   (dinv[d] applied in final). 8 edges/thread.
__global__ void __launch_bounds__(256) msg_kernel(const int* __restrict__ src,
                                                  const int* __restrict__ dst) {
    int t = blockIdx.x * 256 + threadIdx.x;
    if (t >= EGROUPS) return;
    const int4* s4p = (const int4*)src;
    const int4* d4p = (const int4*)dst;
    int4 sa = s4p[t];
    int4 sb = s4p[t + EGROUPS];
    int4 da = d4p[t];
    int4 db = d4p[t + EGROUPS];

    float h0 = __ldg(&g_h[sa.x]);
    float h1 = __ldg(&g_h[sa.y]);
    float h2 = __ldg(&g_h[sa.z]);
    float h3 = __ldg(&g_h[sa.w]);
    float h4 = __ldg(&g_h[sb.x]);
    float h5 = __ldg(&g_h[sb.y]);
    float h6 = __ldg(&g_h[sb.z]);
    float h7 = __ldg(&g_h[sb.w]);

    atomicAdd(&g_gcn[da.x], h0);
    atomicAdd(&g_gcn[da.y], h1);
    atomicAdd(&g_gcn[da.z], h2);
    atomicAdd(&g_gcn[da.w], h3);
    atomicAdd(&g_gcn[db.x], h4);
    atomicAdd(&g_gcn[db.y], h5);
    atomicAdd(&g_gcn[db.z], h6);
    atomicAdd(&g_gcn[db.w], h7);
}

__device__ __forceinline__ float sigmoidf_(float v) {
    return 1.0f / (1.0f + expf(-v));
}

// ---------------------------------------------------------------------------
__global__ void __launch_bounds__(256) final_kernel(
        const float* __restrict__ alpha_p,
        const float* __restrict__ beta_p,
        const float* __restrict__ W_att,
        const float* __restrict__ b_att,
        float* __restrict__ out) {
    int n = blockIdx.x * 256 + threadIdx.x;
    if (n >= N_NODES) return;

    float alpha = __ldg(alpha_p);
    float beta  = __ldg(beta_p);

    float degf = g_degf[n];
    float dinv = rsqrtf(degf + 1.0f);
    // gcn_out = dinv*(sum_s h[s]) + dinv*h[n]   (h[n] = dinv*xw[n])
    float gcn = dinv * (g_gcn[n] + g_h[n]);

    float s1 = sigmoidf_(alpha * sqrtf(degf) + beta);
    float s2 = sigmoidf_(g_xm[n]);
    float s3 = sigmoidf_(gcn + g_xl[n]);

    float l0 = s1 * __ldg(&W_att[0]) + s2 * __ldg(&W_att[1]) + s3 * __ldg(&W_att[2]) + __ldg(&b_att[0]);
    float l1 = s1 * __ldg(&W_att[3]) + s2 * __ldg(&W_att[4]) + s3 * __ldg(&W_att[5]) + __ldg(&b_att[1]);
    float l2 = s1 * __ldg(&W_att[6]) + s2 * __ldg(&W_att[7]) + s3 * __ldg(&W_att[8]) + __ldg(&b_att[2]);

    float m  = fmaxf(l0, fmaxf(l1, l2));
    float e0 = expf(l0 - m), e1 = expf(l1 - m), e2 = expf(l2 - m);
    float inv = 1.0f / (e0 + e1 + e2);
    out[n] = (e0 * s1 + e1 * s2 + e2 * s3) * inv;
}

// ---------------------------------------------------------------------------
extern "C" void kernel_launch(void* const* d_in, const int* in_sizes, int n_in,
                              void* d_out, int out_size) {
    const float* x     = (const float*)d_in[0];
    const int*   eidx  = (const int*)d_in[1];   // [2, N_EDGES] int32
    const float* alpha = (const float*)d_in[2];
    const float* beta  = (const float*)d_in[3];
    const float* Wm    = (const float*)d_in[4];
    const float* Wl    = (const float*)d_in[5];
    const float* Wg    = (const float*)d_in[6];
    const float* Watt  = (const float*)d_in[7];
    const float* batt  = (const float*)d_in[8];
    float* out = (float*)d_out;

    const int* src = eidx;            // edge_index[0]
    const int* dst = eidx + N_EDGES;  // edge_index[1]

    void* degf_ptr = nullptr;
    void* gcn_ptr  = nullptr;
    cudaGetSymbolAddress(&degf_ptr, g_degf);
    cudaGetSymbolAddress(&gcn_ptr,  g_gcn);
    cudaMemsetAsync(degf_ptr, 0, N_NODES * sizeof(float));
    cudaMemsetAsync(gcn_ptr,  0, N_NODES * sizeof(float));

    int nodeBlocks = (N_NODES + 255) / 256;

    fused_dots_deg_kernel<<<DOT_BLOCKS + EDG_BLOCKS, 256>>>(x, Wm, Wl, Wg, dst);
    h_kernel<<<nodeBlocks, 256>>>();
    msg_kernel<<<EDG_BLOCKS, 256>>>(src, dst);
    final_kernel<<<nodeBlocks, 256>>>(alpha, beta, Watt, batt, out);
}